// round 17
// baseline (speedup 1.0000x reference)
#include <cuda_runtime.h>

// Problem constants
#define PB 16384   // batch
#define PN 32      // keypoints
#define PK 16      // mixture components
#define MB 4       // samples per thread
#define TPB 256    // 8 warps: warp = one keypoint n, lane = batch
#define NW 8       // n values per block
#define BTILE (32 * MB)      // 128 consecutive b per block
#define ROWW (NW * 3)        // 24 floats of each kps/out row used by this block
#define ROWP 25              // padded smem row stride (gcd(25,32)=1 -> conflict-free)
#define GOFF (PB * PN * 3)   // grad output offset

// Per-(n,k) params, 3 x float4 each, idx = (n*PK + k)*3:
//  +0: (h0, h1, h2, q00)      h = -Q*mu
//  +1: (q01, q02, q11, q12)
//  +2: (q22, c, 0, 0)         c = mu^T Q mu + lc
// Q = Sigma^{-1} * (-0.5*log2e); earg = x.pd + h.x + c, pd = Qx + h.
__constant__ float4 c_par[PN * PK * 3];   // 24 KB
__device__   float4 g_par[PN * PK * 3];   // staging written by precompute

__global__ void precompute_params(const float* __restrict__ means,
                                  const float* __restrict__ covs,
                                  const float* __restrict__ weights) {
    int t = threadIdx.x;
    if (t >= PN * PK) return;
    int nk = t;                 // coalesced: consecutive threads -> consecutive cov rows
    int n = t >> 4;
    int k = t & 15;

    const float* c = covs + nk * 9;
    float c00 = c[0], c01 = c[1], c02 = c[2];
    float c11 = c[4], c12 = c[5], c22 = c[8];

    float m00 = c11 * c22 - c12 * c12;
    float m01 = c02 * c12 - c01 * c22;
    float m02 = c01 * c12 - c02 * c11;
    float det = c00 * m00 + c01 * m01 + c02 * m02;
    const float NH = -0.72134752044448170f;   // -(0.5*log2 e)
    float inv = NH / det;

    float q00 = m00 * inv;
    float q01 = m01 * inv;
    float q02 = m02 * inv;
    float q11 = (c00 * c22 - c02 * c02) * inv;
    float q12 = (c01 * c02 - c00 * c12) * inv;
    float q22 = (c00 * c11 - c01 * c01) * inv;

    const float TWOPI3 = 248.05021344239853f; // (2*pi)^3
    float lc = log2f(weights[nk]) - 0.5f * log2f(TWOPI3 * det);

    const float* mu = means + nk * 3;
    float mx = mu[0], my = mu[1], mz = mu[2];
    float h0 = -(q00 * mx + q01 * my + q02 * mz);
    float h1 = -(q01 * mx + q11 * my + q12 * mz);
    float h2 = -(q02 * mx + q12 * my + q22 * mz);
    float cc = -(h0 * mx + h1 * my + h2 * mz) + lc;

    int idx = (n * PK + k) * 3;
    g_par[idx + 0] = make_float4(h0, h1, h2, q00);
    g_par[idx + 1] = make_float4(q01, q02, q11, q12);
    g_par[idx + 2] = make_float4(q22, cc, 0.0f, 0.0f);
}

__device__ __forceinline__ float ex2a(float x) {
    float r; asm("ex2.approx.ftz.f32 %0,%1;" : "=f"(r) : "f"(x)); return r;
}
__device__ __forceinline__ float rcpa(float x) {
    float r; asm("rcp.approx.ftz.f32 %0,%1;" : "=f"(r) : "f"(x)); return r;
}

__global__ void gmm_main(const float* __restrict__ kps,
                         float* __restrict__ out) {
    __shared__ float tA[BTILE * ROWP];   // 12.8 KB: kps in, dens out
    __shared__ float tB[BTILE * ROWP];   // 12.8 KB: grad out

    int tid  = threadIdx.x;
    int w    = tid >> 5;                 // warp -> n offset within block
    int lane = tid & 31;                 // lane -> b offset
    int bx = blockIdx.x;
    int n0 = (bx & 3) * NW;
    int b0 = (bx >> 2) * BTILE;

    // ---- stage in: kps tile [BTILE rows][24 cols] (96B row chunks, sector-aligned) ----
#pragma unroll
    for (int it = 0; it < (BTILE * ROWW) / TPB; it++) {
        int f = it * TPB + tid;
        int r = f / ROWW, c = f % ROWW;
        tA[r * ROWP + c] = kps[(size_t)(b0 + r) * (PN * 3) + n0 * 3 + c];
    }
    __syncthreads();

    int n = n0 + w;                      // warp-uniform keypoint index
    float x[MB], y[MB], z[MB];
#pragma unroll
    for (int i = 0; i < MB; i++) {
        int r = i * 32 + lane;
        x[i] = tA[r * ROWP + w * 3 + 0];
        y[i] = tA[r * ROWP + w * 3 + 1];
        z[i] = tA[r * ROWP + w * 3 + 2];
    }
    __syncthreads();                     // tA free for reuse (dens)

    float pdf[MB], gx[MB], gy[MB], gz[MB];
#pragma unroll
    for (int i = 0; i < MB; i++) { pdf[i] = 0.0f; gx[i] = 0.0f; gy[i] = 0.0f; gz[i] = 0.0f; }

    int cb = n * (PK * 3);               // warp-uniform const base

#pragma unroll
    for (int k = 0; k < PK; k++) {
        // warp-uniform constant loads -> LDCU / UR operands
        float4 pa = c_par[cb + k * 3 + 0];   // h0,h1,h2,q00
        float4 pb = c_par[cb + k * 3 + 1];   // q01,q02,q11,q12
        float4 pc = c_par[cb + k * 3 + 2];   // q22, c

#pragma unroll
        for (int i = 0; i < MB; i++) {
            // pd = Q x + h : multiplier is uniform (2-GPR FFMA form)
            float pd0 = fmaf(pa.w, x[i], fmaf(pb.x, y[i], fmaf(pb.y, z[i], pa.x)));
            float pd1 = fmaf(pb.x, x[i], fmaf(pb.z, y[i], fmaf(pb.w, z[i], pa.y)));
            float pd2 = fmaf(pb.y, x[i], fmaf(pb.w, y[i], fmaf(pc.x, z[i], pa.z)));
            float hx  = fmaf(pa.x, x[i], fmaf(pa.y, y[i], fmaf(pa.z, z[i], pc.y)));
            float earg = fmaf(pd0, x[i], fmaf(pd1, y[i], fmaf(pd2, z[i], hx)));
            float e = ex2a(earg);
            pdf[i] += e;
            gx[i] = fmaf(e, pd0, gx[i]);
            gy[i] = fmaf(e, pd1, gy[i]);
            gz[i] = fmaf(e, pd2, gz[i]);
        }
    }

    // ---- epilogue: all threads produce both outputs (no k-split, no shuffles) ----
    const float L2E_OVER_TAU = 0.19235933878519513f;  // log2e / 7.5
    const float MAG_C0 = 7.2134752044448170f;         // 5 * log2 e
    const float MAG_C1 = -1.0f / 550.0f;

#pragma unroll
    for (int i = 0; i < MB; i++) {
        int r = i * 32 + lane;
        float u = ex2a((40.0f - pdf[i]) * L2E_OVER_TAU);
        float s = rcpa(1.0f + u);
        tA[r * ROWP + w * 3 + 0] = s;
        tA[r * ROWP + w * 3 + 1] = s;
        tA[r * ROWP + w * 3 + 2] = s;

        float s2 = fmaf(gx[i], gx[i], fmaf(gy[i], gy[i], gz[i] * gz[i]));
        float rinv = rsqrtf(s2);
        float gs = s2 * rinv;                        // |gacc| = (0.5*log2e)|grad|
        float mag = ex2a(fmaf(gs, MAG_C1, MAG_C0));  // 2^(5*log2e - |gacc|/550)
        float scale = rinv * mag;                    // ETA=1; sign correct
        tB[r * ROWP + w * 3 + 0] = gx[i] * scale;
        tB[r * ROWP + w * 3 + 1] = gy[i] * scale;
        tB[r * ROWP + w * 3 + 2] = gz[i] * scale;
    }
    __syncthreads();

    // ---- stage out: coalesced 96B row-chunk stores for both outputs ----
#pragma unroll
    for (int it = 0; it < (BTILE * ROWW) / TPB; it++) {
        int f = it * TPB + tid;
        int r = f / ROWW, c = f % ROWW;
        size_t o = (size_t)(b0 + r) * (PN * 3) + n0 * 3 + c;
        out[o]        = tA[r * ROWP + c];
        out[GOFF + o] = tB[r * ROWP + c];
    }
}

extern "C" void kernel_launch(void* const* d_in, const int* in_sizes, int n_in,
                              void* d_out, int out_size) {
    const float* kps     = (const float*)d_in[0];
    const float* means   = (const float*)d_in[1];
    const float* covs    = (const float*)d_in[2];
    const float* weights = (const float*)d_in[3];
    float* out = (float*)d_out;

    precompute_params<<<1, 512>>>(means, covs, weights);

    // Move params into constant memory (D2D async copy, graph-capturable).
    void* src = nullptr;
    cudaGetSymbolAddress(&src, g_par);
    cudaMemcpyToSymbolAsync(c_par, src, sizeof(float4) * PN * PK * 3, 0,
                            cudaMemcpyDeviceToDevice, 0);

    int nblocks = (PB / BTILE) * (PN / NW);   // 128 * 4 = 512
    gmm_main<<<nblocks, TPB>>>(kps, out);
}